// round 14
// baseline (speedup 1.0000x reference)
#include <cuda_runtime.h>
#include <cstdint>

#define F_DIM 16384
#define N_BINS 128
#define NT 256
#define N_ROWS 4096
#define N_OUT 64
#define GRID_P (152 * 4)      // persistent: 4 CTAs/SM x 152 SMs (GB300)
#define NW 8                  // warps per CTA
#define N_REG 12              // float4 iterations in registers
#define N_STG 4               // float4 iterations staged via cp.async

// Dynamic smem layout (bytes)
#define SM_HIST  0            // 8 warps * 4096 = 32768
#define SM_STAGE 32768        // 4 * 256 * 16  = 16384
#define SM_RED   49152        // 16 floats     = 64
#define SM_PCNT  49216        // 8 warps * 33 uint4 = 4224
#define SM_CNT   53440        // 128 floats    = 512
#define SM_PART  53952        // 256 floats    = 1024
#define SM_TOTAL 54976

// Prep outputs (allocation-free static scratch)
__device__ float g_wt[N_BINS * N_OUT];   // W[:, :128] transposed to [bin][out]
__device__ float g_s0[N_OUT];            // sum_j W[o][128+j]
__device__ float g_s1[N_OUT];            // sum_j (j/128) W[o][128+j]

__device__ __forceinline__ float f_inf() { return __int_as_float(0x7f800000); }

__device__ __forceinline__ void cp_async16(uint32_t dst_smem, const void* src) {
    asm volatile("cp.async.cg.shared.global [%0], [%1], 16;"
                 :: "r"(dst_smem), "l"(src) : "memory");
}
__device__ __forceinline__ void cp_async_commit() {
    asm volatile("cp.async.commit_group;" ::: "memory");
}
__device__ __forceinline__ void cp_async_wait0() {
    asm volatile("cp.async.wait_group 0;" ::: "memory");
}

// ---------------------------------------------------------------------------
// Prep: one CTA per output o. Transpose counts-half of W to bin-major and
// reduce the 129 boundary weights to S0/S1.
// ---------------------------------------------------------------------------
__global__ __launch_bounds__(128) void prep_kernel(const float* __restrict__ W) {
    __shared__ float sp0[4], sp1[4];
    const int o = blockIdx.x;
    const int tid = threadIdx.x;

    g_wt[tid * N_OUT + o] = W[o * 257 + tid];

    float wv = W[o * 257 + 128 + tid];
    float s0 = wv;
    float s1 = (float)tid * 0.0078125f * wv;     // exact j/128
    if (tid == 0) {
        float w128 = W[o * 257 + 256];
        s0 += w128;
        s1 += w128;                               // t(128) = 1.0
    }
#pragma unroll
    for (int off = 16; off > 0; off >>= 1) {
        s0 += __shfl_xor_sync(0xFFFFFFFFu, s0, off);
        s1 += __shfl_xor_sync(0xFFFFFFFFu, s1, off);
    }
    if ((tid & 31) == 0) { sp0[tid >> 5] = s0; sp1[tid >> 5] = s1; }
    __syncthreads();
    if (tid == 0) {
        g_s0[o] = sp0[0] + sp0[1] + sp0[2] + sp0[3];
        g_s1[o] = sp1[0] + sp1[1] + sp1[2] + sp1[3];
    }
}

// ---------------------------------------------------------------------------
// Persistent fused kernel: NT=256 (8 warps), 4 CTAs/SM -> 4 INDEPENDENT
// rows in flight per SM with narrow 8-warp joins (R13 showed wide joins
// convoy). Per thread: 12 float4 in regs + 4 float4 staged in smem via
// cp.async (never transit registers) -> 64 regs total.
// Warp-private hists, bank-invariant layout: counter (w,b,l) at byte
//   w*4096 + (b>>2)*128 + l*4 + (b&3)  -> word bank = l for ANY bin (CF).
// ---------------------------------------------------------------------------
__global__ __launch_bounds__(NT, 4) void hist_kernel(const float* __restrict__ x,
                                                     const float* __restrict__ bias,
                                                     float* __restrict__ out) {
    extern __shared__ unsigned char smem[];
    unsigned char* s_hist = smem + SM_HIST;
    float* s_red = (float*)(smem + SM_RED);
    uint4* s_pcnt4 = (uint4*)(smem + SM_PCNT);
    float* s_cnt = (float*)(smem + SM_CNT);
    float* s_part = (float*)(smem + SM_PART);

    const int tid = threadIdx.x;
    const int w = tid >> 5;
    const int l = tid & 31;
    int row = blockIdx.x;

    const uint32_t stage_u32 =
        (uint32_t)__cvta_generic_to_shared(smem + SM_STAGE) + (uint32_t)tid * 16u;
    const float4* stage_rd = (const float4*)(smem + SM_STAGE) + tid;

    // ---- Prologue: row 0 -> 12 float4 to regs, 4 float4 via cp.async ----
    float4 rv[N_REG];
    {
        const float4* __restrict__ xr = (const float4*)(x + (size_t)row * F_DIM);
#pragma unroll
        for (int i = 0; i < N_REG; i++) rv[i] = __ldcs(xr + tid + i * NT);
#pragma unroll
        for (int i = 0; i < N_STG; i++)
            cp_async16(stage_u32 + i * (NT * 16), xr + tid + (N_REG + i) * NT);
        cp_async_commit();
    }

    for (;;) {
        const int next = row + GRID_P;
        const bool has_next = (next < N_ROWS);
        const float4* __restrict__ nxt =
            (const float4*)(x + (size_t)(has_next ? next : row) * F_DIM);

        // ---- Warp min/max over 12 reg + 4 staged float4 ----
        float mn = f_inf(), mx = -f_inf();
#pragma unroll
        for (int i = 0; i < N_REG; i++) {
            mn = fminf(mn, fminf(fminf(rv[i].x, rv[i].y), fminf(rv[i].z, rv[i].w)));
            mx = fmaxf(mx, fmaxf(fmaxf(rv[i].x, rv[i].y), fmaxf(rv[i].z, rv[i].w)));
        }
        cp_async_wait0();            // staged quarter resident
#pragma unroll
        for (int i = 0; i < N_STG; i++) {
            const float4 v = stage_rd[i * NT];
            mn = fminf(mn, fminf(fminf(v.x, v.y), fminf(v.z, v.w)));
            mx = fmaxf(mx, fmaxf(fmaxf(v.x, v.y), fmaxf(v.z, v.w)));
        }
#pragma unroll
        for (int o = 16; o > 0; o >>= 1) {
            mn = fminf(mn, __shfl_xor_sync(0xFFFFFFFFu, mn, o));
            mx = fmaxf(mx, __shfl_xor_sync(0xFFFFFFFFu, mx, o));
        }
        if (l == 0) { s_red[w] = mn; s_red[NW + w] = mx; }
        __syncthreads();                               // JOIN A
        {
            float a = s_red[l & 7];
            float b = s_red[NW + (l & 7)];
#pragma unroll
            for (int o = 4; o > 0; o >>= 1) {
                a = fminf(a, __shfl_xor_sync(0xFFFFFFFFu, a, o));
                b = fmaxf(b, __shfl_xor_sync(0xFFFFFFFFu, b, o));
            }
            mn = a; mx = b;
        }
        const float width = mx - mn;
        const float scale = 128.0f / (width == 0.0f ? 1.0f : width);  // matches jnp where()
        const float nb = -mn * scale;

        // ---- Zero own warp hist: 8 STS.128 ----
        {
            uint4* hz = (uint4*)(s_hist + (w << 12));
            uint4 z = make_uint4(0u, 0u, 0u, 0u);
#pragma unroll
            for (int k = 0; k < 8; k++) hz[k * 32 + l] = z;
        }
        __syncwarp();

        // ---- Bin (warp-local, bank-CF byte RMW) ----
        unsigned char* hb = s_hist + (w << 12) + (l << 2);

#define BIN4(v)                                                                \
    {                                                                          \
        const int b0 = (int)fminf(fmaf((v).x, scale, nb), 127.0f);             \
        const int b1 = (int)fminf(fmaf((v).y, scale, nb), 127.0f);             \
        const int b2 = (int)fminf(fmaf((v).z, scale, nb), 127.0f);             \
        const int b3 = (int)fminf(fmaf((v).w, scale, nb), 127.0f);             \
        const int o0 = ((b0 & 124) << 5) + (b0 & 3);                           \
        const int o1 = ((b1 & 124) << 5) + (b1 & 3);                           \
        const int o2 = ((b2 & 124) << 5) + (b2 & 3);                           \
        const int o3 = ((b3 & 124) << 5) + (b3 & 3);                           \
        const unsigned int e02 = (b2 == b0) ? 1u : 0u;                         \
        const unsigned int e13 = (b3 == b1) ? 1u : 0u;                         \
        unsigned int c0 = hb[o0];                                              \
        unsigned int c2 = hb[o2];                                              \
        hb[o0] = (unsigned char)(c0 + 1u + e02);                               \
        if (!e02) hb[o2] = (unsigned char)(c2 + 1u);                           \
        unsigned int c1 = hb[o1];                                              \
        unsigned int c3 = hb[o3];                                              \
        hb[o1] = (unsigned char)(c1 + 1u + e13);                               \
        if (!e13) hb[o3] = (unsigned char)(c3 + 1u);                           \
    }

        // Register part; refill each slot with next row's value as freed
#pragma unroll
        for (int i = 0; i < N_REG; i++) {
            const float4 v = rv[i];
            if (has_next) rv[i] = __ldcs(nxt + tid + i * NT);   // prefetch
            BIN4(v);
        }
        // Staged part (LDS; values already consumed before overwrite below)
#pragma unroll
        for (int i = 0; i < N_STG; i++) {
            const float4 v = stage_rd[i * NT];
            BIN4(v);
        }
#undef BIN4
        // Issue next row's staged quarter (after all staged reads done)
        if (has_next) {
#pragma unroll
            for (int i = 0; i < N_STG; i++)
                cp_async16(stage_u32 + i * (NT * 16), nxt + tid + (N_REG + i) * NT);
            cp_async_commit();
        }
        __syncwarp();

        // ---- Warp-local reduce: lane l owns bins 4l..4l+3 (word row l).
        // Rotated reads (bank (j+l)&31, CF); dp4a byte selectors. ----
        {
            const unsigned int* h32 = (const unsigned int*)(s_hist + (w << 12));
            unsigned int s0 = 0u, s1 = 0u, s2 = 0u, s3 = 0u;
#pragma unroll
            for (int j = 0; j < 32; j++) {
                const unsigned int v32 = h32[(l << 5) + ((j + l) & 31)];
                s0 = __dp4a(v32, 0x00000001u, s0);
                s1 = __dp4a(v32, 0x00000100u, s1);
                s2 = __dp4a(v32, 0x00010000u, s2);
                s3 = __dp4a(v32, 0x01000000u, s3);
            }
            s_pcnt4[w * 33 + l] = make_uint4(s0, s1, s2, s3);   // STS.128
        }
        __syncthreads();                               // JOIN B

        // ---- Combine 8 warps' partials: word (w2, b) = w2*132 + b (CF) ----
        if (tid < N_BINS) {
            const unsigned int* p32 = (const unsigned int*)s_pcnt4;
            int s = 0;
#pragma unroll
            for (int w2 = 0; w2 < NW; w2++) s += (int)p32[w2 * 132 + tid];
            s_cnt[tid] = (float)s;
        }
        __syncthreads();                               // JOIN B2

        // ---- Epilogue: out[row][o] = cnt.Wt/F + mn*S0 + wd*S1 + b ----
        {
            const int o = tid & 63;
            const int q = tid >> 6;                    // 4 chunks of 32 bins
            const float* wt = g_wt + (q * 32) * N_OUT + o;
            float acc = 0.0f;
#pragma unroll
            for (int j = 0; j < 32; j++)
                acc = fmaf(s_cnt[q * 32 + j], __ldg(wt + j * N_OUT), acc);
            s_part[tid] = acc;
        }
        __syncthreads();                               // JOIN C
        if (tid < 64) {
            const float bo = bias[tid];
            float s = (s_part[tid] + s_part[tid + 64]) +
                      (s_part[tid + 128] + s_part[tid + 192]);
            float res = fmaf(s, 1.0f / 16384.0f,
                             fmaf(mn, g_s0[tid], fmaf(width, g_s1[tid], bo)));
            out[(size_t)row * N_OUT + tid] = res;
        }

        if (!has_next) break;
        row = next;
    }
}

// ---------------------------------------------------------------------------
extern "C" void kernel_launch(void* const* d_in, const int* in_sizes, int n_in,
                              void* d_out, int out_size) {
    const float* x = (const float*)d_in[0];
    const float* W = (const float*)d_in[1];
    const float* b = (const float*)d_in[2];
    float* out = (float*)d_out;

    cudaFuncSetAttribute(hist_kernel, cudaFuncAttributeMaxDynamicSharedMemorySize,
                         SM_TOTAL);

    prep_kernel<<<N_OUT, 128>>>(W);
    hist_kernel<<<GRID_P, NT, SM_TOTAL>>>(x, b, out);
}